// round 1
// baseline (speedup 1.0000x reference)
#include <cuda_runtime.h>

#define NSENT 4000
#define LSEQ  128
#define EMBD  60
#define HID   230
#define HIDP  232      // padded channels (29 chunks of 8)
#define NBAG  500
#define NREL  25
#define TT    180      // EMB * 3 (reduction length)
#define ESTRIDE 61     // smem row stride (coprime with 32 -> conflict-free)

// Scratch (device globals; no runtime allocation allowed)
__device__ __align__(16) float g_wT[TT * HIDP];    // transposed, padded conv weights: wT[t][c]
__device__ float g_h[NSENT * HIDP];                // pooled sentence features

// ---------------------------------------------------------------------------
// Prep: transpose conv_w [HID][EMB][3] -> wT[t=d*3+k][c], zero-pad c in [230,232)
// ---------------------------------------------------------------------------
__global__ void prep_w_kernel(const float* __restrict__ conv_w) {
    int i = blockIdx.x * blockDim.x + threadIdx.x;
    if (i >= TT * HIDP) return;
    int t = i / HIDP, c = i - t * HIDP;
    g_wT[i] = (c < HID) ? conv_w[c * TT + t] : 0.f;
}

// ---------------------------------------------------------------------------
// Fused: embedding gather + conv1d(k=3, SAME) + maxpool over L + bias + relu
// One block per sentence. 8 warps: lane -> 4 positions, warp -> channel chunks.
// ---------------------------------------------------------------------------
__global__ __launch_bounds__(256, 2) void conv_kernel(
    const int*   __restrict__ X,
    const int*   __restrict__ P1,
    const int*   __restrict__ P2,
    const float* __restrict__ WE,   // [50002][50]
    const float* __restrict__ E1,   // [201][5]
    const float* __restrict__ E2,   // [201][5]
    const float* __restrict__ conv_b)
{
    __shared__ float es[130 * ESTRIDE];   // rows 0..129 = positions -1..128 (zero-padded ends)
    const int n = blockIdx.x;

    // Gather embeddings into smem (rows 1..128); zero pad rows 0 and 129.
    for (int i = threadIdx.x; i < LSEQ * EMBD; i += 256) {
        int l = i / EMBD, d = i - l * EMBD;
        float v;
        if (d < 50)      v = WE[X[n * LSEQ + l] * 50 + d];
        else if (d < 55) v = E1[P1[n * LSEQ + l] * 5 + (d - 50)];
        else             v = E2[P2[n * LSEQ + l] * 5 + (d - 55)];
        es[(l + 1) * ESTRIDE + d] = v;
    }
    for (int i = threadIdx.x; i < ESTRIDE; i += 256) {
        es[i] = 0.f;
        es[129 * ESTRIDE + i] = 0.f;
    }
    __syncthreads();

    const int lane = threadIdx.x & 31;
    const int warp = threadIdx.x >> 5;

    for (int chunk = warp; chunk < HIDP / 8; chunk += 8) {
        const int c0 = chunk * 8;
        float acc[4][8];
        #pragma unroll
        for (int j = 0; j < 4; j++)
            #pragma unroll
            for (int c = 0; c < 8; c++) acc[j][c] = 0.f;

        #pragma unroll 1
        for (int d = 0; d < EMBD; d++) {
            // emb values for this thread's 4 positions x 3 taps (conflict-free LDS)
            float e[4][3];
            #pragma unroll
            for (int j = 0; j < 4; j++) {
                int rb = (lane + 32 * j) * ESTRIDE + d;
                e[j][0] = es[rb];
                e[j][1] = es[rb + ESTRIDE];
                e[j][2] = es[rb + 2 * ESTRIDE];
            }
            #pragma unroll
            for (int kk = 0; kk < 3; kk++) {
                const float4* wp = (const float4*)(g_wT + (d * 3 + kk) * HIDP + c0);
                float4 wa = wp[0], wb = wp[1];
                float w8[8] = { wa.x, wa.y, wa.z, wa.w, wb.x, wb.y, wb.z, wb.w };
                #pragma unroll
                for (int j = 0; j < 4; j++)
                    #pragma unroll
                    for (int c = 0; c < 8; c++)
                        acc[j][c] = fmaf(e[j][kk], w8[c], acc[j][c]);
            }
        }

        // max over 4 positions, then over 32 lanes (=128 positions); bias + relu
        #pragma unroll
        for (int c = 0; c < 8; c++) {
            float m = fmaxf(fmaxf(acc[0][c], acc[1][c]), fmaxf(acc[2][c], acc[3][c]));
            #pragma unroll
            for (int off = 16; off; off >>= 1)
                m = fmaxf(m, __shfl_xor_sync(0xffffffffu, m, off));
            if (lane == 0) {
                int cg = c0 + c;
                float b = (cg < HID) ? conv_b[cg] : 0.f;
                g_h[n * HIDP + cg] = fmaxf(m + b, 0.f);
            }
        }
    }
}

// ---------------------------------------------------------------------------
// Per-bag attention pooling + classifier. One block per bag (bag size <= 8).
// ---------------------------------------------------------------------------
__global__ __launch_bounds__(256) void bag_kernel(
    const int*   __restrict__ scope,
    const int*   __restrict__ relation,
    const float* __restrict__ rel_w,   // [NREL][HID]
    const float* __restrict__ rel_b,   // [NREL]
    float*       __restrict__ out)     // [NBAG][NREL]
{
    __shared__ float q[HID];
    __shared__ float rep[HID];
    __shared__ float logit[8];
    __shared__ float alpha[8];

    const int b   = blockIdx.x;
    const int rel = relation[b];
    const int s0  = scope[2 * b];
    int ns        = scope[2 * b + 1] - s0;
    if (ns > 8) ns = 8;

    for (int t = threadIdx.x; t < HID; t += 256) q[t] = rel_w[rel * HID + t];
    __syncthreads();

    const int lane = threadIdx.x & 31;
    const int warp = threadIdx.x >> 5;

    // logits: warp s computes dot(h[s0+s], q)
    {
        float p = 0.f;
        if (warp < ns) {
            const float* hr = g_h + (size_t)(s0 + warp) * HIDP;
            for (int c = lane; c < HID; c += 32) p += hr[c] * q[c];
        }
        #pragma unroll
        for (int off = 16; off; off >>= 1) p += __shfl_xor_sync(0xffffffffu, p, off);
        if (lane == 0 && warp < 8) logit[warp] = (warp < ns) ? p : -1e30f;
    }
    __syncthreads();

    // softmax over <=8 sentences (serial, trivial)
    if (threadIdx.x == 0) {
        float m = -1e30f;
        for (int s = 0; s < ns; s++) m = fmaxf(m, logit[s]);
        float den = 0.f;
        for (int s = 0; s < ns; s++) { float e = expf(logit[s] - m); alpha[s] = e; den += e; }
        float inv = 1.f / den;
        for (int s = 0; s < ns; s++) alpha[s] *= inv;
    }
    __syncthreads();

    // bag_rep = sum_s alpha[s] * h[s0+s]
    for (int t = threadIdx.x; t < HID; t += 256) {
        float r = 0.f;
        for (int s = 0; s < ns; s++)
            r = fmaf(alpha[s], g_h[(size_t)(s0 + s) * HIDP + t], r);
        rep[t] = r;
    }
    __syncthreads();

    // out[b][r] = rep . rel_w[r] + rel_b[r]
    for (int r = warp; r < NREL; r += 8) {
        float p = 0.f;
        const float* wr = rel_w + r * HID;
        for (int c = lane; c < HID; c += 32) p += rep[c] * wr[c];
        #pragma unroll
        for (int off = 16; off; off >>= 1) p += __shfl_xor_sync(0xffffffffu, p, off);
        if (lane == 0) out[b * NREL + r] = p + rel_b[r];
    }
}

// ---------------------------------------------------------------------------
// Inputs (metadata order): X, pos1, pos2, mask, length, scope, relation,
//   word_emb, pos1_emb, pos2_emb, conv_w, conv_b, rel_w, rel_b
// ---------------------------------------------------------------------------
extern "C" void kernel_launch(void* const* d_in, const int* in_sizes, int n_in,
                              void* d_out, int out_size)
{
    const int*   X        = (const int*)d_in[0];
    const int*   P1       = (const int*)d_in[1];
    const int*   P2       = (const int*)d_in[2];
    const int*   scope    = (const int*)d_in[5];
    const int*   relation = (const int*)d_in[6];
    const float* WE       = (const float*)d_in[7];
    const float* E1       = (const float*)d_in[8];
    const float* E2       = (const float*)d_in[9];
    const float* conv_w   = (const float*)d_in[10];
    const float* conv_b   = (const float*)d_in[11];
    const float* rel_w    = (const float*)d_in[12];
    const float* rel_b    = (const float*)d_in[13];
    float*       out      = (float*)d_out;

    prep_w_kernel<<<(TT * HIDP + 255) / 256, 256>>>(conv_w);
    conv_kernel<<<NSENT, 256>>>(X, P1, P2, WE, E1, E2, conv_b);
    bag_kernel<<<NBAG, 256>>>(scope, relation, rel_w, rel_b, out);
}